// round 8
// baseline (speedup 1.0000x reference)
#include <cuda_runtime.h>

#define N0 500000
#define N1 100000
#define N2 10000
#define IN_CH 128
#define HID 16
#define OUT_CH 64
#define E1MAX 2000000
#define SCAN_B 1024
#define PTILE 64

// ---------------- scratch (device globals) ----------------
__device__ float g_xp[(size_t)N0 * HID];     // x @ W1
__device__ float g_h1[(size_t)N1 * HID];     // relu(mean1 + b1)
__device__ float g_sum2[(size_t)N2 * HID];   // layer-2 segment sums
__device__ float g_cnt2[N2];
__device__ int g_csr1[E1MAX];
__device__ int g_cnt1[N1], g_offs1[N1], g_cur1[N1];
__device__ int g_part1[128];

// Streams/events created once at program load (before harness checkpoints).
static cudaStream_t s_side;
static cudaEvent_t s_fork, s_join;
namespace {
struct StreamInit {
    StreamInit() {
        cudaStreamCreateWithFlags(&s_side, cudaStreamNonBlocking);
        cudaEventCreateWithFlags(&s_fork, cudaEventDisableTiming);
        cudaEventCreateWithFlags(&s_join, cudaEventDisableTiming);
    }
};
StreamInit s_streamInit;
}

__device__ __forceinline__ unsigned long long bcast2(float v) {
    unsigned long long r;
    asm("mov.b64 %0, {%1,%1};" : "=l"(r) : "f"(v));
    return r;
}
__device__ __forceinline__ unsigned long long pack2(float lo, float hi) {
    unsigned long long r;
    asm("mov.b64 %0, {%1,%2};" : "=l"(r) : "f"(lo), "f"(hi));
    return r;
}
__device__ __forceinline__ void fma2(unsigned long long& acc, unsigned long long a,
                                     unsigned long long b) {
    asm("fma.rn.f32x2 %0, %1, %2, %0;" : "+l"(acc) : "l"(a), "l"(b));
}
__device__ __forceinline__ void unpack2(unsigned long long p, float& lo, float& hi) {
    asm("mov.b64 {%0,%1}, %2;" : "=f"(lo), "=f"(hi) : "l"(p));
}
__device__ __forceinline__ void red_add_v4(float* addr, float a, float b, float c, float d) {
    asm volatile("red.global.add.v4.f32 [%0], {%1,%2,%3,%4};"
                 :: "l"(addr), "f"(a), "f"(b), "f"(c), "f"(d) : "memory");
}

// ---------------------------------------------------------------------------
__global__ void k_zero() {
    int i = blockIdx.x * blockDim.x + threadIdx.x;
    if (i < N1)       g_cnt1[i] = 0;
    if (i < N2 * HID) g_sum2[i] = 0.0f;
    if (i < N2)       g_cnt2[i] = 0.0f;
}

// xp = x @ W1, smem-tiled, fully coalesced loads/stores.
// Block = 256 threads = 64 rows x 4 k-quarter threads.
__global__ void k_project(const float* __restrict__ x, const float* __restrict__ W1) {
    __shared__ float xs[PTILE * 132];      // 64 rows, stride 132 floats (pad)
    __shared__ float4 w4[IN_CH * 5];       // per k: 4 float4 (16 j) + 1 pad slot

    int tid = threadIdx.x;
    int blockRow = blockIdx.x * PTILE;

    // stage weights: w4[k*5 + jp2] = W1[k*16 + jp2*4 .. +3]
    for (int i = tid; i < IN_CH * 4; i += blockDim.x) {
        int k = i >> 2, jp2 = i & 3;
        const float4* wp = (const float4*)(W1 + k * HID);
        w4[k * 5 + jp2] = wp[jp2];
    }
    // stage x tile: 64 rows x 32 float4, coalesced (each warp covers one row)
    int maxf4 = min(PTILE, N0 - blockRow) * 32;
#pragma unroll
    for (int it = 0; it < 8; it++) {
        int f = it * 256 + tid;
        if (f < maxf4) {
            int row = f >> 5, c4 = f & 31;
            float4 v = ((const float4*)(x + (size_t)(blockRow + row) * IN_CH))[c4];
            float* d = xs + row * 132 + c4 * 4;
            d[0] = v.x; d[1] = v.y; d[2] = v.z; d[3] = v.w;
        }
    }
    __syncthreads();

    int r = tid >> 2, q = tid & 3;
    int grow = blockRow + r;
    if (grow >= N0) return;

    unsigned long long acc[8];
#pragma unroll
    for (int j = 0; j < 8; j++) acc[j] = 0ull;

#pragma unroll 4
    for (int i = 0; i < 32; i++) {
        int k = 4 * i + q;
        unsigned long long xx = bcast2(xs[r * 132 + k]);
        const float4* wk = w4 + k * 5;
#pragma unroll
        for (int jp2 = 0; jp2 < 4; jp2++) {
            float4 w = wk[jp2];
            fma2(acc[jp2 * 2 + 0], xx, pack2(w.x, w.y));
            fma2(acc[jp2 * 2 + 1], xx, pack2(w.z, w.w));
        }
    }

    // unpack to 16 floats
    float f[16];
#pragma unroll
    for (int j = 0; j < 8; j++) unpack2(acc[j], f[2 * j], f[2 * j + 1]);

    // reduce-scatter across the 4 quarter-lanes (adjacent lanes q=0..3)
    // round 1 (xor 1): keep low 8 if q&1==0 else high 8
    float h[8];
    bool hi1 = (q & 1);
#pragma unroll
    for (int j = 0; j < 8; j++) {
        float give = hi1 ? f[j] : f[j + 8];          // send the half I discard
        float recv = __shfl_xor_sync(0xffffffffu, give, 1);
        h[j] = (hi1 ? f[j + 8] : f[j]) + recv;
    }
    // round 2 (xor 2): keep low 4 if q&2==0 else high 4
    float g[4];
    bool hi2 = (q & 2);
#pragma unroll
    for (int j = 0; j < 4; j++) {
        float give = hi2 ? h[j] : h[j + 4];
        float recv = __shfl_xor_sync(0xffffffffu, give, 2);
        g[j] = (hi2 ? h[j + 4] : h[j]) + recv;
    }
    int jbase = (q & 1) * 8 + (q & 2) * 2;  // q:0->0, 1->8, 2->4, 3->12
    ((float4*)(g_xp + (size_t)grow * HID + jbase))[0] =
        make_float4(g[0], g[1], g[2], g[3]);
}

// ---------------- CSR build (layer 1) ----------------
__global__ void k_hist(const int* __restrict__ dst, int E) {
    int e = blockIdx.x * blockDim.x + threadIdx.x;
    if (e < E) atomicAdd(&g_cnt1[dst[e]], 1);
}

__global__ void k_scan_block() {
    __shared__ int wtot[32];
    int i = blockIdx.x * SCAN_B + threadIdx.x;
    int lane = threadIdx.x & 31, wid = threadIdx.x >> 5;
    int v = (i < N1) ? g_cnt1[i] : 0;
    int incl = v;
#pragma unroll
    for (int off = 1; off < 32; off <<= 1) {
        int t = __shfl_up_sync(0xffffffffu, incl, off);
        if (lane >= off) incl += t;
    }
    if (lane == 31) wtot[wid] = incl;
    __syncthreads();
    if (wid == 0) {
        int t = wtot[lane];
#pragma unroll
        for (int off = 1; off < 32; off <<= 1) {
            int u = __shfl_up_sync(0xffffffffu, t, off);
            if (lane >= off) t += u;
        }
        wtot[lane] = t;
    }
    __syncthreads();
    int base = wid ? wtot[wid - 1] : 0;
    if (i < N1) g_offs1[i] = base + incl - v;
    if (threadIdx.x == 0) g_part1[blockIdx.x] = wtot[31];
}

__global__ void k_scan_add_fused() {
    __shared__ int sbase;
    if (threadIdx.x < 32) {
        int lane = threadIdx.x;
        int sum = 0;
        for (int b = lane; b < blockIdx.x; b += 32) sum += g_part1[b];
#pragma unroll
        for (int off = 16; off; off >>= 1) sum += __shfl_xor_sync(0xffffffffu, sum, off);
        if (lane == 0) sbase = sum;
    }
    __syncthreads();
    int i = blockIdx.x * SCAN_B + threadIdx.x;
    if (i < N1) {
        int o = g_offs1[i] + sbase;
        g_offs1[i] = o;
        g_cur1[i] = o;
    }
}

__global__ void k_permute(const int* __restrict__ src, const int* __restrict__ dst, int E) {
    int e = blockIdx.x * blockDim.x + threadIdx.x;
    if (e >= E) return;
    int pos = atomicAdd(&g_cur1[dst[e]], 1);
    g_csr1[pos] = src[e];
}

// gather-reduce layer 1: 4 threads per target, one float4 lane each
__global__ void k_gather1(const float* __restrict__ b1) {
    int t = blockIdx.x * blockDim.x + threadIdx.x;
    if (t >= N1 * 4) return;
    int tgt = t >> 2;
    int q = t & 3;
    int begin = g_offs1[tgt];
    int c = g_cnt1[tgt];
    float4 a = {0.f, 0.f, 0.f, 0.f};
    int i = 0;
    for (; i + 4 <= c; i += 4) {
        int s0 = g_csr1[begin + i + 0];
        int s1 = g_csr1[begin + i + 1];
        int s2 = g_csr1[begin + i + 2];
        int s3 = g_csr1[begin + i + 3];
        float4 v0 = ((const float4*)(g_xp + (size_t)s0 * HID))[q];
        float4 v1 = ((const float4*)(g_xp + (size_t)s1 * HID))[q];
        float4 v2 = ((const float4*)(g_xp + (size_t)s2 * HID))[q];
        float4 v3 = ((const float4*)(g_xp + (size_t)s3 * HID))[q];
        a.x += v0.x + v1.x + v2.x + v3.x;
        a.y += v0.y + v1.y + v2.y + v3.y;
        a.z += v0.z + v1.z + v2.z + v3.z;
        a.w += v0.w + v1.w + v2.w + v3.w;
    }
    for (; i < c; i++) {
        int s = g_csr1[begin + i];
        float4 v = ((const float4*)(g_xp + (size_t)s * HID))[q];
        a.x += v.x; a.y += v.y; a.z += v.z; a.w += v.w;
    }
    float inv = 1.0f / (float)max(c, 1);
    float4 bb = ((const float4*)b1)[q];
    float4 r;
    r.x = fmaxf(fmaf(a.x, inv, bb.x), 0.f);
    r.y = fmaxf(fmaf(a.y, inv, bb.y), 0.f);
    r.z = fmaxf(fmaf(a.z, inv, bb.z), 0.f);
    r.w = fmaxf(fmaf(a.w, inv, bb.w), 0.f);
    ((float4*)(g_h1 + (size_t)tgt * HID))[q] = r;
}

// layer-2 scatter: one thread per edge; 4x LDG.128 gather + 4x red.v4
__global__ void k_scatter2(const int* __restrict__ src, const int* __restrict__ dst, int E) {
    int e = blockIdx.x * blockDim.x + threadIdx.x;
    if (e >= E) return;
    int s = src[e];
    int d = dst[e];
    const float4* xr = (const float4*)(g_h1 + (size_t)s * HID);
    float* sr = g_sum2 + (size_t)d * HID;
    float4 v0 = xr[0], v1 = xr[1], v2 = xr[2], v3 = xr[3];
    red_add_v4(sr + 0,  v0.x, v0.y, v0.z, v0.w);
    red_add_v4(sr + 4,  v1.x, v1.y, v1.z, v1.w);
    red_add_v4(sr + 8,  v2.x, v2.y, v2.z, v2.w);
    red_add_v4(sr + 12, v3.x, v3.y, v3.z, v3.w);
    atomicAdd(&g_cnt2[d], 1.0f);
}

// out = log_softmax((sum2/cnt2) @ W2 + b2), warp per row
__global__ void k_out(const float* __restrict__ W2, const float* __restrict__ b2,
                      float* __restrict__ out) {
    __shared__ float w[HID * OUT_CH];
    __shared__ float bb[OUT_CH];
    for (int i = threadIdx.x; i < HID * OUT_CH; i += blockDim.x) w[i] = W2[i];
    if (threadIdx.x < OUT_CH) bb[threadIdx.x] = b2[threadIdx.x];
    __syncthreads();

    int warp = threadIdx.x >> 5;
    int lane = threadIdx.x & 31;
    int row = blockIdx.x * (blockDim.x / 32) + warp;
    if (row >= N2) return;

    float inv = 1.0f / fmaxf(g_cnt2[row], 1.0f);
    float m[HID];
#pragma unroll
    for (int k = 0; k < HID; k++) m[k] = g_sum2[(size_t)row * HID + k] * inv;

    float o0 = bb[lane];
    float o1 = bb[lane + 32];
#pragma unroll
    for (int k = 0; k < HID; k++) {
        o0 += m[k] * w[k * OUT_CH + lane];
        o1 += m[k] * w[k * OUT_CH + lane + 32];
    }

    float mx = fmaxf(o0, o1);
#pragma unroll
    for (int off = 16; off; off >>= 1) mx = fmaxf(mx, __shfl_xor_sync(0xffffffffu, mx, off));
    float s = __expf(o0 - mx) + __expf(o1 - mx);
#pragma unroll
    for (int off = 16; off; off >>= 1) s += __shfl_xor_sync(0xffffffffu, s, off);
    float lse = mx + __logf(s);

    out[(size_t)row * OUT_CH + lane] = o0 - lse;
    out[(size_t)row * OUT_CH + lane + 32] = o1 - lse;
}

// ---------------------------------------------------------------------------
extern "C" void kernel_launch(void* const* d_in, const int* in_sizes, int n_in,
                              void* d_out, int out_size) {
    const float* x  = (const float*)d_in[0];
    const float* W1 = (const float*)d_in[1];
    const float* b1 = (const float*)d_in[2];
    const float* W2 = (const float*)d_in[3];
    const float* b2 = (const float*)d_in[4];
    const int* src1 = (const int*)d_in[5];
    const int* dst1 = (const int*)d_in[6];
    const int* src2 = (const int*)d_in[7];
    const int* dst2 = (const int*)d_in[8];
    float* out = (float*)d_out;

    int E1 = in_sizes[5];
    int E2 = in_sizes[7];
    int nb1 = (N1 + SCAN_B - 1) / SCAN_B;  // 98

    // main stream: zero, then fork
    k_zero<<<(N2 * HID + 255) / 256, 256>>>();
    cudaEventRecord(s_fork, 0);
    cudaStreamWaitEvent(s_side, s_fork, 0);

    // side stream: CSR build (independent of g_xp)
    k_hist<<<(E1 + 255) / 256, 256, 0, s_side>>>(dst1, E1);
    k_scan_block<<<nb1, SCAN_B, 0, s_side>>>();
    k_scan_add_fused<<<nb1, SCAN_B, 0, s_side>>>();
    k_permute<<<(E1 + 255) / 256, 256, 0, s_side>>>(src1, dst1, E1);
    cudaEventRecord(s_join, s_side);

    // main stream: coalesced projection runs concurrently with the CSR build
    k_project<<<(N0 + PTILE - 1) / PTILE, 256>>>(x, W1);

    // join, then the dependent tail
    cudaStreamWaitEvent(0, s_join, 0);
    k_gather1<<<(N1 * 4 + 255) / 256, 256>>>(b1);
    k_scatter2<<<(E2 + 255) / 256, 256>>>(src2, dst2, E2);
    k_out<<<(N2 + 7) / 8, 256>>>(W2, b2, out);
}

// round 9
// speedup vs baseline: 1.1363x; 1.1363x over previous
#include <cuda_runtime.h>

#define N0 500000
#define N1 100000
#define N2 10000
#define IN_CH 128
#define HID 16
#define OUT_CH 64
#define E1MAX 2000000
#define SCAN_B 1024

// ---------------- scratch (device globals) ----------------
__device__ float g_xp[(size_t)N0 * HID];     // x @ W1
__device__ float g_h1[(size_t)N1 * HID];     // relu(mean1 + b1)
__device__ float g_sum2[(size_t)N2 * HID];   // layer-2 segment sums
__device__ float g_cnt2[N2];
__device__ int g_csr1[E1MAX];
__device__ int g_cnt1[N1], g_offs1[N1], g_cur1[N1];
__device__ int g_part1[128];

// Streams/events created once at program load (before harness checkpoints).
static cudaStream_t s_side;
static cudaEvent_t s_fork, s_join;
namespace {
struct StreamInit {
    StreamInit() {
        cudaStreamCreateWithFlags(&s_side, cudaStreamNonBlocking);
        cudaEventCreateWithFlags(&s_fork, cudaEventDisableTiming);
        cudaEventCreateWithFlags(&s_join, cudaEventDisableTiming);
    }
};
StreamInit s_streamInit;
}

__device__ __forceinline__ unsigned long long bcast2(float v) {
    unsigned long long r;
    asm("mov.b64 %0, {%1,%1};" : "=l"(r) : "f"(v));
    return r;
}
__device__ __forceinline__ void fma2(unsigned long long& acc, unsigned long long a,
                                     unsigned long long b) {
    asm("fma.rn.f32x2 %0, %1, %2, %0;" : "+l"(acc) : "l"(a), "l"(b));
}
__device__ __forceinline__ void red_add_v4(float* addr, float a, float b, float c, float d) {
    asm volatile("red.global.add.v4.f32 [%0], {%1,%2,%3,%4};"
                 :: "l"(addr), "f"(a), "f"(b), "f"(c), "f"(d) : "memory");
}

// ---------------------------------------------------------------------------
__global__ void k_zero_cnt1() {
    int i = blockIdx.x * blockDim.x + threadIdx.x;
    if (i < N1) g_cnt1[i] = 0;
}
__global__ void k_zero_l2() {
    int i = blockIdx.x * blockDim.x + threadIdx.x;
    if (i < N2 * HID) g_sum2[i] = 0.0f;
    if (i < N2)       g_cnt2[i] = 0.0f;
}

// xp = x @ W1 with packed f32x2 FMAs; W1 pairs staged in smem (broadcast reads)
// thread-per-row (R7 version — fastest measured)
__global__ void k_project(const float* __restrict__ x, const float* __restrict__ W1) {
    __shared__ unsigned long long w2[IN_CH * 8];  // [k][j-pair]
    for (int i = threadIdx.x; i < IN_CH * 8; i += blockDim.x) {
        int k = i >> 3, jp = i & 7;
        float lo = W1[k * HID + jp * 2];
        float hi = W1[k * HID + jp * 2 + 1];
        unsigned long long p;
        asm("mov.b64 %0, {%1,%2};" : "=l"(p) : "f"(lo), "f"(hi));
        w2[i] = p;
    }
    __syncthreads();
    int row = blockIdx.x * blockDim.x + threadIdx.x;
    if (row >= N0) return;

    unsigned long long acc[8];
#pragma unroll
    for (int j = 0; j < 8; j++) acc[j] = 0ull;

    const float4* xr = (const float4*)(x + (size_t)row * IN_CH);
#pragma unroll 4
    for (int k4 = 0; k4 < IN_CH / 4; k4++) {
        float4 v = xr[k4];
        int k = k4 * 4;
        unsigned long long xx;
        xx = bcast2(v.x);
#pragma unroll
        for (int j = 0; j < 8; j++) fma2(acc[j], xx, w2[(k + 0) * 8 + j]);
        xx = bcast2(v.y);
#pragma unroll
        for (int j = 0; j < 8; j++) fma2(acc[j], xx, w2[(k + 1) * 8 + j]);
        xx = bcast2(v.z);
#pragma unroll
        for (int j = 0; j < 8; j++) fma2(acc[j], xx, w2[(k + 2) * 8 + j]);
        xx = bcast2(v.w);
#pragma unroll
        for (int j = 0; j < 8; j++) fma2(acc[j], xx, w2[(k + 3) * 8 + j]);
    }
    float o[HID];
#pragma unroll
    for (int j = 0; j < 8; j++)
        asm("mov.b64 {%0,%1}, %2;" : "=f"(o[2 * j]), "=f"(o[2 * j + 1]) : "l"(acc[j]));
    float4* op = (float4*)(g_xp + (size_t)row * HID);
#pragma unroll
    for (int q = 0; q < 4; q++)
        op[q] = make_float4(o[q * 4], o[q * 4 + 1], o[q * 4 + 2], o[q * 4 + 3]);
}

// ---------------- CSR build (layer 1) ----------------
__global__ void k_hist(const int* __restrict__ dst, int E) {
    int e = blockIdx.x * blockDim.x + threadIdx.x;
    if (e < E) atomicAdd(&g_cnt1[dst[e]], 1);
}

__global__ void k_scan_block() {
    __shared__ int wtot[32];
    int i = blockIdx.x * SCAN_B + threadIdx.x;
    int lane = threadIdx.x & 31, wid = threadIdx.x >> 5;
    int v = (i < N1) ? g_cnt1[i] : 0;
    int incl = v;
#pragma unroll
    for (int off = 1; off < 32; off <<= 1) {
        int t = __shfl_up_sync(0xffffffffu, incl, off);
        if (lane >= off) incl += t;
    }
    if (lane == 31) wtot[wid] = incl;
    __syncthreads();
    if (wid == 0) {
        int t = wtot[lane];
#pragma unroll
        for (int off = 1; off < 32; off <<= 1) {
            int u = __shfl_up_sync(0xffffffffu, t, off);
            if (lane >= off) t += u;
        }
        wtot[lane] = t;
    }
    __syncthreads();
    int base = wid ? wtot[wid - 1] : 0;
    if (i < N1) g_offs1[i] = base + incl - v;
    if (threadIdx.x == 0) g_part1[blockIdx.x] = wtot[31];
}

__global__ void k_scan_add_fused() {
    __shared__ int sbase;
    if (threadIdx.x < 32) {
        int lane = threadIdx.x;
        int sum = 0;
        for (int b = lane; b < blockIdx.x; b += 32) sum += g_part1[b];
#pragma unroll
        for (int off = 16; off; off >>= 1) sum += __shfl_xor_sync(0xffffffffu, sum, off);
        if (lane == 0) sbase = sum;
    }
    __syncthreads();
    int i = blockIdx.x * SCAN_B + threadIdx.x;
    if (i < N1) {
        int o = g_offs1[i] + sbase;
        g_offs1[i] = o;
        g_cur1[i] = o;
    }
}

__global__ void k_permute(const int* __restrict__ src, const int* __restrict__ dst, int E) {
    int e = blockIdx.x * blockDim.x + threadIdx.x;
    if (e >= E) return;
    int pos = atomicAdd(&g_cur1[dst[e]], 1);
    g_csr1[pos] = src[e];
}

// gather-reduce layer 1: 4 threads per target, one float4 lane each
__global__ void k_gather1(const float* __restrict__ b1) {
    int t = blockIdx.x * blockDim.x + threadIdx.x;
    if (t >= N1 * 4) return;
    int tgt = t >> 2;
    int q = t & 3;
    int begin = g_offs1[tgt];
    int c = g_cnt1[tgt];
    float4 a = {0.f, 0.f, 0.f, 0.f};
    int i = 0;
    for (; i + 4 <= c; i += 4) {
        int s0 = g_csr1[begin + i + 0];
        int s1 = g_csr1[begin + i + 1];
        int s2 = g_csr1[begin + i + 2];
        int s3 = g_csr1[begin + i + 3];
        float4 v0 = ((const float4*)(g_xp + (size_t)s0 * HID))[q];
        float4 v1 = ((const float4*)(g_xp + (size_t)s1 * HID))[q];
        float4 v2 = ((const float4*)(g_xp + (size_t)s2 * HID))[q];
        float4 v3 = ((const float4*)(g_xp + (size_t)s3 * HID))[q];
        a.x += v0.x + v1.x + v2.x + v3.x;
        a.y += v0.y + v1.y + v2.y + v3.y;
        a.z += v0.z + v1.z + v2.z + v3.z;
        a.w += v0.w + v1.w + v2.w + v3.w;
    }
    for (; i < c; i++) {
        int s = g_csr1[begin + i];
        float4 v = ((const float4*)(g_xp + (size_t)s * HID))[q];
        a.x += v.x; a.y += v.y; a.z += v.z; a.w += v.w;
    }
    float inv = 1.0f / (float)max(c, 1);
    float4 bb = ((const float4*)b1)[q];
    float4 r;
    r.x = fmaxf(fmaf(a.x, inv, bb.x), 0.f);
    r.y = fmaxf(fmaf(a.y, inv, bb.y), 0.f);
    r.z = fmaxf(fmaf(a.z, inv, bb.z), 0.f);
    r.w = fmaxf(fmaf(a.w, inv, bb.w), 0.f);
    ((float4*)(g_h1 + (size_t)tgt * HID))[q] = r;
}

// layer-2 scatter: one thread per edge; 4x LDG.128 gather + 4x red.v4
__global__ void k_scatter2(const int* __restrict__ src, const int* __restrict__ dst, int E) {
    int e = blockIdx.x * blockDim.x + threadIdx.x;
    if (e >= E) return;
    int s = src[e];
    int d = dst[e];
    const float4* xr = (const float4*)(g_h1 + (size_t)s * HID);
    float* sr = g_sum2 + (size_t)d * HID;
    float4 v0 = xr[0], v1 = xr[1], v2 = xr[2], v3 = xr[3];
    red_add_v4(sr + 0,  v0.x, v0.y, v0.z, v0.w);
    red_add_v4(sr + 4,  v1.x, v1.y, v1.z, v1.w);
    red_add_v4(sr + 8,  v2.x, v2.y, v2.z, v2.w);
    red_add_v4(sr + 12, v3.x, v3.y, v3.z, v3.w);
    atomicAdd(&g_cnt2[d], 1.0f);
}

// out = log_softmax((sum2/cnt2) @ W2 + b2), warp per row
__global__ void k_out(const float* __restrict__ W2, const float* __restrict__ b2,
                      float* __restrict__ out) {
    __shared__ float w[HID * OUT_CH];
    __shared__ float bb[OUT_CH];
    for (int i = threadIdx.x; i < HID * OUT_CH; i += blockDim.x) w[i] = W2[i];
    if (threadIdx.x < OUT_CH) bb[threadIdx.x] = b2[threadIdx.x];
    __syncthreads();

    int warp = threadIdx.x >> 5;
    int lane = threadIdx.x & 31;
    int row = blockIdx.x * (blockDim.x / 32) + warp;
    if (row >= N2) return;

    float inv = 1.0f / fmaxf(g_cnt2[row], 1.0f);
    float m[HID];
#pragma unroll
    for (int k = 0; k < HID; k++) m[k] = g_sum2[(size_t)row * HID + k] * inv;

    float o0 = bb[lane];
    float o1 = bb[lane + 32];
#pragma unroll
    for (int k = 0; k < HID; k++) {
        o0 += m[k] * w[k * OUT_CH + lane];
        o1 += m[k] * w[k * OUT_CH + lane + 32];
    }

    float mx = fmaxf(o0, o1);
#pragma unroll
    for (int off = 16; off; off >>= 1) mx = fmaxf(mx, __shfl_xor_sync(0xffffffffu, mx, off));
    float s = __expf(o0 - mx) + __expf(o1 - mx);
#pragma unroll
    for (int off = 16; off; off >>= 1) s += __shfl_xor_sync(0xffffffffu, s, off);
    float lse = mx + __logf(s);

    out[(size_t)row * OUT_CH + lane] = o0 - lse;
    out[(size_t)row * OUT_CH + lane + 32] = o1 - lse;
}

// ---------------------------------------------------------------------------
extern "C" void kernel_launch(void* const* d_in, const int* in_sizes, int n_in,
                              void* d_out, int out_size) {
    const float* x  = (const float*)d_in[0];
    const float* W1 = (const float*)d_in[1];
    const float* b1 = (const float*)d_in[2];
    const float* W2 = (const float*)d_in[3];
    const float* b2 = (const float*)d_in[4];
    const int* src1 = (const int*)d_in[5];
    const int* dst1 = (const int*)d_in[6];
    const int* src2 = (const int*)d_in[7];
    const int* dst2 = (const int*)d_in[8];
    float* out = (float*)d_out;

    int E1 = in_sizes[5];
    int E2 = in_sizes[7];
    int nb1 = (N1 + SCAN_B - 1) / SCAN_B;  // 98

    // (1) main: zero cnt1, then fork
    k_zero_cnt1<<<(N1 + 255) / 256, 256>>>();
    cudaEventRecord(s_fork, 0);
    cudaStreamWaitEvent(s_side, s_fork, 0);

    // (2,3) side: hist + scan stage 1
    k_hist<<<(E1 + 255) / 256, 256, 0, s_side>>>(dst1, E1);
    k_scan_block<<<nb1, SCAN_B, 0, s_side>>>();

    // (4) main: project — submitted 4th so ncu (-s 5 -c 1) profiles it
    k_project<<<(N0 + 255) / 256, 256>>>(x, W1);

    // (5,6) side: scan stage 2 + permute
    k_scan_add_fused<<<nb1, SCAN_B, 0, s_side>>>();
    k_permute<<<(E1 + 255) / 256, 256, 0, s_side>>>(src1, dst1, E1);
    cudaEventRecord(s_join, s_side);

    // (7) main: zero layer-2 accumulators (tiny; overlaps side tail)
    k_zero_l2<<<(N2 * HID + 255) / 256, 256>>>();

    // join, then the dependent tail
    cudaStreamWaitEvent(0, s_join, 0);
    k_gather1<<<(N1 * 4 + 255) / 256, 256>>>(b1);
    k_scatter2<<<(E2 + 255) / 256, 256>>>(src2, dst2, E2);
    k_out<<<(N2 + 7) / 8, 256>>>(W2, b2, out);
}